// round 7
// baseline (speedup 1.0000x reference)
#include <cuda_runtime.h>
#include <math.h>

// Problem constants
#define NR   2048
#define L    128
#define FGV  2.0f

// Tiling
#define RPB      16                  // rows per chunk
#define THREADS  256
#define WPB      8                   // warps per block
#define BPC      5                   // blocks per chunk (40 warps of work)
#define NCHUNKS  (NR / RPB)          // 128
#define GRID     (BPC * NCHUNKS)     // 640
#define PADF     32                  // overread pad (j reaches 151 on last row)

// Per-block partials (overwritten every launch -> deterministic)
__device__ float    g_part[GRID];
__device__ float    g_fpart[GRID];
__device__ unsigned g_ctr = 0;       // wraps to 0 via atomicInc every launch

// ---- f32x2 / b64 helpers (sm_103a) ----
typedef unsigned long long u64;
__device__ __forceinline__ u64 splat2f(float v) {
    u64 r; asm("mov.b64 %0,{%1,%1};" : "=l"(r) : "f"(v)); return r;
}
__device__ __forceinline__ u64 splat2u(unsigned v) {
    u64 r; asm("mov.b64 %0,{%1,%1};" : "=l"(r) : "r"(v)); return r;
}
__device__ __forceinline__ void upk2(u64 v, float& lo, float& hi) {
    asm("mov.b64 {%0,%1},%2;" : "=f"(lo), "=f"(hi) : "l"(v));
}
__device__ __forceinline__ u64 fma2(u64 a, u64 b, u64 c) {
    u64 r; asm("fma.rn.f32x2 %0,%1,%2,%3;" : "=l"(r) : "l"(a), "l"(b), "l"(c)); return r;
}
__device__ __forceinline__ u64 add2(u64 a, u64 b) {
    u64 r; asm("add.rn.f32x2 %0,%1,%2;" : "=l"(r) : "l"(a), "l"(b)); return r;
}
#define ONEBITS 0x3f800000u          // bit pattern of 1.0f

__global__ __launch_bounds__(THREADS, 5) void loss_k(
        const float* __restrict__ y_true,
        const float* __restrict__ y_pred,
        const float* __restrict__ y_diff,
        const float* __restrict__ wts,
        float* __restrict__ out)
{
    __shared__ float    ds[RPB * L + PADF];   // raw d = y_true - y_pred
    __shared__ unsigned ms[RPB * L + PADF];   // mask: ~0 if |y_diff|<=2 else 0
    __shared__ float redp[WPB];
    __shared__ float redf[WPB];
    __shared__ bool  s_last;

    const int tid  = threadIdx.x;
    const int bx   = blockIdx.x;
    const int nch  = bx / BPC;            // row chunk
    const int bic  = bx - nch * BPC;      // block-in-chunk 0..4
    const int n0   = nch * RPB;
    const int lane = tid & 31;
    const int wid  = tid >> 5;

    // ---- diag weights (k==0 column of both p-planes), one block per chunk ----
    float w0d[4], w1d[4];
    const int c4 = tid & 31;
    if (bic == 0) {
#pragma unroll
        for (int s = 0; s < 4; s++) {
            const int c = 4 * c4 + s;
            w0d[s] = wts[c * L];
            w1d[s] = wts[L * L + c * L];
        }
    }

    // ---- stage d, mask into smem; fold diagonal term + f-sum (bic==0) ----
    float floc  = 0.0f;
    float dpart = 0.0f;
    {
        const float4* yt4 = (const float4*)y_true + (size_t)n0 * (L / 4);
        const float4* yp4 = (const float4*)y_pred + (size_t)n0 * (L / 4);
        const float4* yd4 = (const float4*)y_diff + (size_t)n0 * (L / 4);
#pragma unroll
        for (int it = 0; it < RPB * L / 4 / THREADS; it++) {
            const int idx = tid + it * THREADS;
            const float4 t = yt4[idx];
            const float4 p = yp4[idx];
            const float4 q = yd4[idx];
            float    d[4]; unsigned m[4];
            d[0] = t.x - p.x; d[1] = t.y - p.y; d[2] = t.z - p.z; d[3] = t.w - p.w;
            m[0] = (fabsf(q.x) > FGV) ? 0u : 0xffffffffu;
            m[1] = (fabsf(q.y) > FGV) ? 0u : 0xffffffffu;
            m[2] = (fabsf(q.z) > FGV) ? 0u : 0xffffffffu;
            m[3] = (fabsf(q.w) > FGV) ? 0u : 0xffffffffu;
            if (bic == 0) {
#pragma unroll
                for (int s = 0; s < 4; s++) {
                    // f as float: mask & bits(1.0f); e = d & mask
                    floc += __uint_as_float(m[s] & ONEBITS);
                    const float e = __uint_as_float(__float_as_uint(d[s]) & m[s]);
                    dpart += fabsf(e) * w0d[s] + e * e * w1d[s];
                }
            }
            float4 d4; uint4 m4;
            d4.x = d[0]; d4.y = d[1]; d4.z = d[2]; d4.w = d[3];
            m4.x = m[0]; m4.y = m[1]; m4.z = m[2]; m4.w = m[3];
            ((float4*)ds)[idx] = d4;
            ((uint4*)ms)[idx]  = m4;
        }
    }
    if (tid < PADF) { ds[RPB * L + tid] = 0.0f; ms[RPB * L + tid] = 0u; }
    __syncthreads();

    // ---- warp -> (8-wide i-band a, j-quadrant wq); 40 warps per chunk ----
    const int gw = bic * WPB + wid;       // 0..39
    int a, wq;
    if (gw < 16)      { a = gw >> 2;               wq = gw & 3; }
    else if (gw < 28) { a = 4  + (gw - 16) / 3;    wq = (gw - 16) % 3; }
    else if (gw < 36) { a = 8  + ((gw - 28) >> 1); wq = (gw - 28) & 1; }
    else              { a = 12 + (gw - 36);        wq = 0; }
    const int i0 = 8 * a;                 // 32B-aligned i base
    const int j  = i0 + 32 * wq + lane;   // this lane's j (>= L slots masked)

    // ---- hot loop: |v| & m_i & m_j|abs  (one LOP3) ; 3 FMA2 per pair ----
    u64 S1[4] = {0, 0, 0, 0}, S2[4] = {0, 0, 0, 0};
    const float*    jr = ds + j;
    const unsigned* jm = ms + j;
    const ulonglong2* di = (const ulonglong2*)(ds + i0);   // 32B aligned pairs
    const ulonglong2* mi = (const ulonglong2*)(ms + i0);
#pragma unroll
    for (int r = 0; r < RPB; r++) {
        const float    dj = jr[r * L];
        const unsigned mj = jm[r * L];
        const ulonglong2 da = di[r * (L / 4)];      // (d0,d1),(d2,d3)
        const ulonglong2 db = di[r * (L / 4) + 1];  // (d4,d5),(d6,d7)
        const ulonglong2 ma = mi[r * (L / 4)];
        const ulonglong2 mb = mi[r * (L / 4) + 1];
        const u64 ndj2  = splat2f(-dj);
        const u64 mja2  = splat2u(mj & 0x7fffffffu);   // mask pre-ANDed with abs
        const u64 di2[4] = { da.x, da.y, db.x, db.y };
        const u64 mi2[4] = { ma.x, ma.y, mb.x, mb.y };
#pragma unroll
        for (int p = 0; p < 4; p++) {
            const u64 v  = add2(di2[p], ndj2);          // d_i - d_j
            const u64 ua = (v & mi2[p]) & mja2;         // LOP3: f_i f_j |d_i-d_j|
            S1[p] = add2(S1[p], ua);                    // p = 1
            S2[p] = fma2(ua, ua, S2[p]);                // p = 2 (|u|^2 = u^2)
        }
    }

    // ---- epilogue: unpack, apply weights once, mask invalid slots ----
    float S1f[8], S2f[8];
#pragma unroll
    for (int p = 0; p < 4; p++) {
        upk2(S1[p], S1f[2 * p], S1f[2 * p + 1]);
        upk2(S2[p], S2f[2 * p], S2f[2 * p + 1]);
    }
    float part = (bic == 0) ? dpart : 0.0f;
#pragma unroll
    for (int s = 0; s < 8; s++) {
        const int  i     = i0 + s;
        const int  k     = j - i;                 // k>=1 live; k==0 in staging
        const bool valid = (k >= 1) && (j < L);
        const int  kc    = min(max(k, 1), L - 1);
        const float w0 = wts[i * L + kc];
        const float w1 = wts[L * L + i * L + kc];
        part += (valid ? 1.0f : 0.0f) * (w0 * S1f[s] + w1 * S2f[s]);
    }

    // ---- block reduction -> per-block partial ----
#pragma unroll
    for (int o = 16; o > 0; o >>= 1) {
        part += __shfl_xor_sync(0xffffffffu, part, o);
        floc += __shfl_xor_sync(0xffffffffu, floc, o);
    }
    if (lane == 0) { redp[wid] = part; redf[wid] = floc; }
    __syncthreads();
    if (tid == 0) {
        float p = 0.0f, ff = 0.0f;
#pragma unroll
        for (int w = 0; w < WPB; w++) { p += redp[w]; ff += redf[w]; }
        g_part[bx]  = p;
        g_fpart[bx] = ff;
        __threadfence();
        const unsigned old = atomicInc(&g_ctr, GRID - 1);   // wraps each launch
        s_last = (old == GRID - 1);
    }
    __syncthreads();

    // ---- last block finalizes ----
    if (s_last) {
        __threadfence();
        double lp = 0.0;
        float  fp = 0.0f;
        for (int idx = tid; idx < GRID; idx += THREADS) {
            lp += (double)g_part[idx];
            fp += g_fpart[idx];
        }
#pragma unroll
        for (int o = 16; o > 0; o >>= 1) {
            lp += __shfl_xor_sync(0xffffffffu, lp, o);
            fp += __shfl_xor_sync(0xffffffffu, fp, o);
        }
        __shared__ double dred[WPB];
        __shared__ float  fred[WPB];
        if (lane == 0) { dred[wid] = lp; fred[wid] = fp; }
        __syncthreads();
        if (tid == 0) {
            double lt = 0.0; float ft = 0.0f;
#pragma unroll
            for (int w = 0; w < WPB; w++) { lt += dred[w]; ft += fred[w]; }
            // loss/l/(n*mean(f)) == total / sum(f); f counted once per chunk
            out[0] = (float)(lt / (double)ft);
        }
    }
}

extern "C" void kernel_launch(void* const* d_in, const int* in_sizes, int n_in,
                              void* d_out, int out_size)
{
    const float* y_true  = (const float*)d_in[0];
    const float* y_pred  = (const float*)d_in[1];
    const float* y_diff  = (const float*)d_in[2];
    const float* weights = (const float*)d_in[3];
    loss_k<<<GRID, THREADS>>>(y_true, y_pred, y_diff, weights, (float*)d_out);
}

// round 8
// speedup vs baseline: 1.1789x; 1.1789x over previous
#include <cuda_runtime.h>
#include <math.h>

// Problem constants
#define NR   2048
#define L    128
#define FGV  2.0f

// Tiling
#define RPB      16                  // rows per chunk
#define THREADS  256
#define WPB      8                   // warps per block
#define BPC      5                   // blocks per chunk (40 warps of work)
#define NCHUNKS  (NR / RPB)          // 128
#define GRID     (BPC * NCHUNKS)     // 640
#define PADF     32                  // overread pad (j reaches 151 on last row)

// Per-block partials: (loss, fsum) packed (overwritten every launch)
__device__ float2   g_pf[GRID];
__device__ unsigned g_ctr = 0;       // wraps to 0 via atomicInc every launch

// ---- f32x2 packed helpers (sm_103a) ----
typedef unsigned long long u64;
__device__ __forceinline__ u64 pk2(float lo, float hi) {
    u64 r; asm("mov.b64 %0,{%1,%2};" : "=l"(r) : "f"(lo), "f"(hi)); return r;
}
__device__ __forceinline__ void upk2(u64 v, float& lo, float& hi) {
    asm("mov.b64 {%0,%1},%2;" : "=f"(lo), "=f"(hi) : "l"(v));
}
__device__ __forceinline__ u64 mul2(u64 a, u64 b) {
    u64 r; asm("mul.rn.f32x2 %0,%1,%2;" : "=l"(r) : "l"(a), "l"(b)); return r;
}
__device__ __forceinline__ u64 fma2(u64 a, u64 b, u64 c) {
    u64 r; asm("fma.rn.f32x2 %0,%1,%2,%3;" : "=l"(r) : "l"(a), "l"(b), "l"(c)); return r;
}
__device__ __forceinline__ u64 add2(u64 a, u64 b) {
    u64 r; asm("add.rn.f32x2 %0,%1,%2;" : "=l"(r) : "l"(a), "l"(b)); return r;
}
#define ABSMASK2 0x7fffffff7fffffffULL

__global__ __launch_bounds__(THREADS) void loss_k(
        const float* __restrict__ y_true,
        const float* __restrict__ y_pred,
        const float* __restrict__ y_diff,
        const float* __restrict__ wts,
        float* __restrict__ out)
{
    __shared__ float es[RPB * L + PADF];    // e = f * d
    __shared__ float fsm[RPB * L + PADF];   // f
    __shared__ float redp[WPB];
    __shared__ float redf[WPB];
    __shared__ bool  s_last;

    const int tid  = threadIdx.x;
    const int bx   = blockIdx.x;
    const int nch  = bx / BPC;            // row chunk
    const int bic  = bx - nch * BPC;      // block-in-chunk 0..4
    const int n0   = nch * RPB;
    const int lane = tid & 31;
    const int wid  = tid >> 5;

    // ---- (1) front-batch ALL staging global loads into registers ----
    float4 T[2], P[2], Q[2];
    {
        const float4* yt4 = (const float4*)y_true + (size_t)n0 * (L / 4);
        const float4* yp4 = (const float4*)y_pred + (size_t)n0 * (L / 4);
        const float4* yd4 = (const float4*)y_diff + (size_t)n0 * (L / 4);
#pragma unroll
        for (int it = 0; it < 2; it++) {
            const int idx = tid + it * THREADS;
            T[it] = yt4[idx];
            P[it] = yp4[idx];
            Q[it] = yd4[idx];
        }
    }

    // ---- warp -> (8-wide i-band a, j-quadrant wq); 40 warps per chunk ----
    const int gw = bic * WPB + wid;       // 0..39
    int a, wq;
    if (gw < 16)      { a = gw >> 2;               wq = gw & 3; }
    else if (gw < 28) { a = 4  + (gw - 16) / 3;    wq = (gw - 16) % 3; }
    else if (gw < 36) { a = 8  + ((gw - 28) >> 1); wq = (gw - 28) & 1; }
    else              { a = 12 + (gw - 36);        wq = 0; }
    const int i0 = 8 * a;                 // 32B-aligned i base
    const int j  = i0 + 32 * wq + lane;   // this lane's j (>= L slots masked)

    // ---- (2) preload epilogue weights NOW: latency hides under hot loop ----
    float w0r[8], w1r[8];
#pragma unroll
    for (int s = 0; s < 8; s++) {
        const int i  = i0 + s;
        const int kc = min(max(j - i, 1), L - 1);
        w0r[s] = wts[i * L + kc];
        w1r[s] = wts[L * L + i * L + kc];
    }

    // ---- diag weights (k==0 column), one block per chunk ----
    float w0d[4], w1d[4];
    const int c4 = tid & 31;
    if (bic == 0) {
#pragma unroll
        for (int s = 0; s < 4; s++) {
            const int c = 4 * c4 + s;
            w0d[s] = wts[c * L];
            w1d[s] = wts[L * L + c * L];
        }
    }

    // ---- stage e, f into smem; fold diagonal term + f-sum (bic==0 only) ----
    float floc  = 0.0f;
    float dpart = 0.0f;
#pragma unroll
    for (int it = 0; it < 2; it++) {
        const int idx = tid + it * THREADS;
        float e[4], f[4];
        e[0] = T[it].x - P[it].x; e[1] = T[it].y - P[it].y;
        e[2] = T[it].z - P[it].z; e[3] = T[it].w - P[it].w;
        f[0] = (fabsf(Q[it].x) > FGV) ? 0.0f : 1.0f;
        f[1] = (fabsf(Q[it].y) > FGV) ? 0.0f : 1.0f;
        f[2] = (fabsf(Q[it].z) > FGV) ? 0.0f : 1.0f;
        f[3] = (fabsf(Q[it].w) > FGV) ? 0.0f : 1.0f;
#pragma unroll
        for (int s = 0; s < 4; s++) {
            e[s] *= f[s];
            if (bic == 0) {
                floc  += f[s];
                dpart += fabsf(e[s]) * w0d[s] + e[s] * e[s] * w1d[s];
            }
        }
        float4 e4, f4;
        e4.x = e[0]; e4.y = e[1]; e4.z = e[2]; e4.w = e[3];
        f4.x = f[0]; f4.y = f[1]; f4.z = f[2]; f4.w = f[3];
        ((float4*)es)[idx]  = e4;
        ((float4*)fsm)[idx] = f4;
    }
    if (tid < PADF) { es[RPB * L + tid] = 0.0f; fsm[RPB * L + tid] = 0.0f; }
    __syncthreads();

    // ---- hot loop: f32x2 pairs, packs loaded pre-paired from smem ----
    u64 S1[4] = {0, 0, 0, 0}, S2[4] = {0, 0, 0, 0};
    const float* er = es  + j;
    const float* fr = fsm + j;
    const ulonglong2* ei = (const ulonglong2*)(es  + i0);   // 32B aligned
    const ulonglong2* fi = (const ulonglong2*)(fsm + i0);
#pragma unroll
    for (int r = 0; r < RPB; r++) {
        const float ej = er[r * L];
        const float fj = fr[r * L];
        const ulonglong2 ea = ei[r * (L / 4)];      // (e0,e1),(e2,e3) packed
        const ulonglong2 eb = ei[r * (L / 4) + 1];  // (e4,e5),(e6,e7)
        const ulonglong2 fa = fi[r * (L / 4)];
        const ulonglong2 fb = fi[r * (L / 4) + 1];
        const float nej = -ej;
        const u64 nej2 = pk2(nej, nej);
        const u64 fj2  = pk2(fj, fj);
        const u64 ei2[4] = { ea.x, ea.y, eb.x, eb.y };
        const u64 fi2[4] = { fa.x, fa.y, fb.x, fb.y };
#pragma unroll
        for (int p = 0; p < 4; p++) {
            const u64 t = mul2(nej2, fi2[p]);       // -e_j * f_i   (pair)
            const u64 u = fma2(ei2[p], fj2, t);     // e_i f_j - e_j f_i
            S1[p] = add2(S1[p], u & ABSMASK2);      // p = 1 (abs on ALU pipe)
            S2[p] = fma2(u, u, S2[p]);              // p = 2 (yf^2 = yf)
        }
    }

    // ---- epilogue: unpack, apply preloaded weights, mask invalid slots ----
    float S1f[8], S2f[8];
#pragma unroll
    for (int p = 0; p < 4; p++) {
        upk2(S1[p], S1f[2 * p], S1f[2 * p + 1]);
        upk2(S2[p], S2f[2 * p], S2f[2 * p + 1]);
    }
    float part = (bic == 0) ? dpart : 0.0f;
#pragma unroll
    for (int s = 0; s < 8; s++) {
        const int  k     = j - (i0 + s);          // k>=1 live; k==0 in staging
        const bool valid = (k >= 1) && (j < L);
        part += (valid ? 1.0f : 0.0f) * (w0r[s] * S1f[s] + w1r[s] * S2f[s]);
    }

    // ---- block reduction -> per-block partial ----
#pragma unroll
    for (int o = 16; o > 0; o >>= 1) {
        part += __shfl_xor_sync(0xffffffffu, part, o);
        floc += __shfl_xor_sync(0xffffffffu, floc, o);
    }
    if (lane == 0) { redp[wid] = part; redf[wid] = floc; }
    __syncthreads();
    if (tid == 0) {
        float p = 0.0f, ff = 0.0f;
#pragma unroll
        for (int w = 0; w < WPB; w++) { p += redp[w]; ff += redf[w]; }
        g_pf[bx] = make_float2(p, ff);
        __threadfence();
        const unsigned old = atomicInc(&g_ctr, GRID - 1);   // wraps each launch
        s_last = (old == GRID - 1);
    }
    __syncthreads();

    // ---- last block finalizes ----
    if (s_last) {
        __threadfence();
        double lp = 0.0;
        float  fp = 0.0f;
        for (int idx = tid; idx < GRID; idx += THREADS) {
            const float2 v = g_pf[idx];
            lp += (double)v.x;
            fp += v.y;
        }
#pragma unroll
        for (int o = 16; o > 0; o >>= 1) {
            lp += __shfl_xor_sync(0xffffffffu, lp, o);
            fp += __shfl_xor_sync(0xffffffffu, fp, o);
        }
        __shared__ double dred[WPB];
        __shared__ float  fred[WPB];
        if (lane == 0) { dred[wid] = lp; fred[wid] = fp; }
        __syncthreads();
        if (tid == 0) {
            double lt = 0.0; float ft = 0.0f;
#pragma unroll
            for (int w = 0; w < WPB; w++) { lt += dred[w]; ft += fred[w]; }
            // loss/l/(n*mean(f)) == total / sum(f); f counted once per chunk
            out[0] = (float)(lt / (double)ft);
        }
    }
}

extern "C" void kernel_launch(void* const* d_in, const int* in_sizes, int n_in,
                              void* d_out, int out_size)
{
    const float* y_true  = (const float*)d_in[0];
    const float* y_pred  = (const float*)d_in[1];
    const float* y_diff  = (const float*)d_in[2];
    const float* weights = (const float*)d_in[3];
    loss_k<<<GRID, THREADS>>>(y_true, y_pred, y_diff, weights, (float*)d_out);
}